// round 3
// baseline (speedup 1.0000x reference)
#include <cuda_runtime.h>
#include <cuda_bf16.h>

// custom_loss_57956288692862
// x: [16384,1024] fp32 -> 4096 groups of 4 rows: q=4b+0, a=4b+1, dead=4b+2, c=4b+3
// target: [2,4096] int32
// out fp32[4097]: out[0]=mean loss, out[1+b]=eq flag
//
// One WARP per group, 2 groups/warp, grid=256 x 256thr -> single wave at 2 CTAs/SM.
// ALL 24 LDG.128 of a group are front-batched (96 data regs) so each warp keeps
// 12KB in flight -> ~49KB/SM, ~2x the DRAM latency-hiding knee (~25KB/SM).

#define NB 4096
#define D  1024
#define THREADS 256
#define GRID 256
#define WARPS_TOTAL (GRID * 8)          // 2048
#define GROUPS_PER_WARP 2               // 2048 * 2 = 4096

__global__ void zero_out0_kernel(float* out) {
    if (threadIdx.x == 0) out[0] = 0.0f;
}

__device__ __forceinline__ float warp_sum(float v) {
    #pragma unroll
    for (int off = 16; off > 0; off >>= 1)
        v += __shfl_xor_sync(0xFFFFFFFFu, v, off);
    return v;
}

__global__ __launch_bounds__(THREADS, 2)
void loss_kernel(const float* __restrict__ x,
                 const int* __restrict__ target,
                 float* __restrict__ out,
                 int out_size) {
    const int t   = threadIdx.x;
    const int wid = t >> 5;
    const int lid = t & 31;
    const int warpGlobal = blockIdx.x * 8 + wid;

    float locLoss = 0.0f;   // lane 0 accumulates across its groups

    #pragma unroll
    for (int gi = 0; gi < GROUPS_PER_WARP; gi++) {
        const int b = warpGlobal + gi * WARPS_TOTAL;

        // Group base: 4 rows * 1024 floats = 1024 float4; row stride = 256 float4.
        const float4* __restrict__ g =
            reinterpret_cast<const float4*>(x + (size_t)b * (4 * D));

        // ---- Front-batch ALL 24 loads (8 float4 per row x 3 rows) ----
        float4 q4[8], a4[8], c4[8];
        #pragma unroll
        for (int j = 0; j < 8; j++) {
            const int idx = lid + 32 * j;
            q4[j] = g[idx];          // row 4b+0
        }
        #pragma unroll
        for (int j = 0; j < 8; j++) {
            const int idx = lid + 32 * j;
            a4[j] = g[256 + idx];    // row 4b+1
        }
        #pragma unroll
        for (int j = 0; j < 8; j++) {
            const int idx = lid + 32 * j;
            c4[j] = g[768 + idx];    // row 4b+3
        }

        // ---- 6 accumulators over 32 floats/lane ----
        float nq = 0.f, na = 0.f, nc = 0.f, qa = 0.f, ac = 0.f, qc = 0.f;
        #pragma unroll
        for (int j = 0; j < 8; j++) {
            nq = fmaf(q4[j].x, q4[j].x, nq); nq = fmaf(q4[j].y, q4[j].y, nq);
            nq = fmaf(q4[j].z, q4[j].z, nq); nq = fmaf(q4[j].w, q4[j].w, nq);
            na = fmaf(a4[j].x, a4[j].x, na); na = fmaf(a4[j].y, a4[j].y, na);
            na = fmaf(a4[j].z, a4[j].z, na); na = fmaf(a4[j].w, a4[j].w, na);
            nc = fmaf(c4[j].x, c4[j].x, nc); nc = fmaf(c4[j].y, c4[j].y, nc);
            nc = fmaf(c4[j].z, c4[j].z, nc); nc = fmaf(c4[j].w, c4[j].w, nc);
            qa = fmaf(q4[j].x, a4[j].x, qa); qa = fmaf(q4[j].y, a4[j].y, qa);
            qa = fmaf(q4[j].z, a4[j].z, qa); qa = fmaf(q4[j].w, a4[j].w, qa);
            ac = fmaf(a4[j].x, c4[j].x, ac); ac = fmaf(a4[j].y, c4[j].y, ac);
            ac = fmaf(a4[j].z, c4[j].z, ac); ac = fmaf(a4[j].w, c4[j].w, ac);
            qc = fmaf(q4[j].x, c4[j].x, qc); qc = fmaf(q4[j].y, c4[j].y, qc);
            qc = fmaf(q4[j].z, c4[j].z, qc); qc = fmaf(q4[j].w, c4[j].w, qc);
        }

        // Warp butterfly reduction (no smem, no block sync)
        nq = warp_sum(nq); na = warp_sum(na); nc = warp_sum(nc);
        qa = warp_sum(qa); ac = warp_sum(ac); qc = warp_sum(qc);

        if (lid == 0) {
            float iq = 1.0f / fmaxf(sqrtf(nq), 1e-12f);
            float ia = 1.0f / fmaxf(sqrtf(na), 1e-12f);
            float ic = 1.0f / fmaxf(sqrtf(nc), 1e-12f);

            float dqa = qa * iq * ia;
            float dac = ac * ia * ic;
            float dqc = qc * iq * ic;

            float t0 = (float)target[b];
            float t1 = (float)target[NB + b];

            float eqa = __expf(dqa);
            float eac = __expf(dac);
            float eqc = __expf(dqc);

            float up   = fmaxf((1.0f - t0) * eqa + (1.0f - t1) * eqc, 1e-8f);
            float down = fmaxf(t0 * eqa + t1 * eqc, 1e-8f);

            locLoss += __logf(up + eac) - __logf(down);

            int correct = (dqa > dqc) ? 1 : 0;
            float eq = (correct == (int)t0) ? 1.0f : 0.0f;
            if (1 + b < out_size) out[1 + b] = eq;
        }
    }

    // Per-CTA aggregation: 8 warp-lane0 partials -> one atomic per CTA
    __shared__ float s[8];
    if (lid == 0) s[wid] = locLoss;
    __syncthreads();
    if (t == 0) {
        float sum = 0.f;
        #pragma unroll
        for (int w = 0; w < 8; w++) sum += s[w];
        atomicAdd(&out[0], sum * (1.0f / (float)NB));
    }
}

extern "C" void kernel_launch(void* const* d_in, const int* in_sizes, int n_in,
                              void* d_out, int out_size) {
    const float* x      = (const float*)d_in[0];
    const int*   target = (const int*)d_in[1];
    float*       out    = (float*)d_out;

    zero_out0_kernel<<<1, 32>>>(out);
    loss_kernel<<<GRID, THREADS>>>(x, target, out, out_size);
}